// round 10
// baseline (speedup 1.0000x reference)
#include <cuda_runtime.h>
#include <cuda_bf16.h>

// NeRF renderer: 16384 rays, 64 coarse + 64 importance samples, 3->64->{1,3} MLP.
// One warp per ray. Piecewise-linear-in-z MLP (affine fold + sorted breakpoints
// + prefix table). This round: ALL rank queries inverted — breakpoints compute
// their own insertion positions (arithmetic for the uniform coarse grid,
// 2 searches/lane into zall for fine) and ranks come from histogram + warp
// scan. sKey eliminated; 36 divergent LDS searches/lane -> 14.

#define N_RAYS   16384
#define WARPS_PB 4
#define BLOCKS   (N_RAYS / WARPS_PB)
#define FULLMASK 0xffffffffu

typedef unsigned long long u64;
typedef unsigned int u32;

__device__ __forceinline__ u64 pk2(float lo, float hi) {
    u64 r;
    asm("mov.b64 %0, {%1, %2};" : "=l"(r) : "f"(lo), "f"(hi));
    return r;
}
__device__ __forceinline__ void upk2(u64 v, float& lo, float& hi) {
    asm("mov.b64 {%0, %1}, %2;" : "=f"(lo), "=f"(hi) : "l"(v));
}
__device__ __forceinline__ u64 add2(u64 a, u64 b) {
    u64 d;
    asm("add.rn.f32x2 %0, %1, %2;" : "=l"(d) : "l"(a), "l"(b));
    return d;
}

__device__ __forceinline__ float softplusf(float x) {
    return x > 20.0f ? x : __logf(1.0f + __expf(x));
}
__device__ __forceinline__ float sigmoidf(float x) {
    return __fdividef(1.0f, 1.0f + __expf(-x));
}
__device__ __forceinline__ float clamp1(float x) {
    return fminf(fmaxf(x, -1.0f), 1.0f);
}
// order-preserving float->u32 (unsigned compare == float compare)
__device__ __forceinline__ u32 ford(float f) {
    u32 b = __float_as_uint(f);
    return (b & 0x80000000u) ? ~b : (b | 0x80000000u);
}
__device__ __forceinline__ float unford(u32 k) {
    return (k & 0x80000000u) ? __uint_as_float(k & 0x7FFFFFFFu)
                             : __uint_as_float(~k);
}
// Coarse z grid: used identically everywhere.
__device__ __forceinline__ float zg(float near, float span, int i) {
    return __fadd_rn(near, __fmul_rn(span, __fmul_rn((float)i, 1.0f / 63.0f)));
}
// first k with u_k=(2k+1)/128 >= c, clamped to [0,64]
__device__ __forceinline__ int kfun(float c) {
    int k = (int)ceilf(__fmul_rn(64.0f, c) - 0.5f);
    return max(0, min(64, k));
}

__global__ __launch_bounds__(128, 9) void nerf_render_kernel(
    const float* __restrict__ rays_o,
    const float* __restrict__ rays_d,
    const float* __restrict__ W1,      // [3,64]
    const float* __restrict__ b1,      // [64]
    const float* __restrict__ w_sigma, // [64,1]
    const float* __restrict__ b_sigma, // [1]
    const float* __restrict__ W_rgb,   // [64,3]
    const float* __restrict__ b_rgb,   // [3]
    float* __restrict__ out)           // [N_RAYS,3]
{
    // sBuf rows padded to 12 floats (48B).
    // Phase A: rows 0..63 = per-unit delta rows. Phase B: rows 0..64 = prefix table.
    __shared__ __align__(16) float sBuf[WARPS_PB][65][12];
    __shared__ __align__(16) u32 hist[WARPS_PB][128];  // reused 3x
    __shared__ __align__(16) float zall[WARPS_PB][128];

    const int tid  = threadIdx.x;
    const int w    = tid >> 5;
    const int lane = tid & 31;
    const int ray  = blockIdx.x * WARPS_PB + w;

    const float bS = b_sigma[0];
    const float bR = b_rgb[0];
    const float bG = b_rgb[1];
    const float bB = b_rgb[2];

    // ---- ray setup (redundant across lanes) ----
    float ox = rays_o[3 * ray + 0], oy = rays_o[3 * ray + 1], oz = rays_o[3 * ray + 2];
    float dx = rays_d[3 * ray + 0], dy = rays_d[3 * ray + 1], dz = rays_d[3 * ray + 2];
    float inv = rsqrtf(dx * dx + dy * dy + dz * dz);
    dx *= inv; dy *= inv; dz *= inv;

    float t0x = (-1.0f - ox) / (dx + 1e-15f), t1x = (1.0f - ox) / (dx + 1e-15f);
    float t0y = (-1.0f - oy) / (dy + 1e-15f), t1y = (1.0f - oy) / (dy + 1e-15f);
    float t0z = (-1.0f - oz) / (dz + 1e-15f), t1z = (1.0f - oz) / (dz + 1e-15f);
    float lox = fminf(t0x, t1x), hix = fmaxf(t0x, t1x);
    float loy = fminf(t0y, t1y), hiy = fmaxf(t0y, t1y);
    float loz = fminf(t0z, t1z), hiz = fmaxf(t0z, t1z);
    float near = fmaxf(lox, fmaxf(loy, loz));
    float far  = fminf(hix, fminf(hiy, hiz));
    bool miss = (far < near);
    if (miss) { near = 1e9f; far = 1e9f; }
    near = fmaxf(near, 0.05f);
    float span = far - near;
    float sample_dist = span * (1.0f / 64.0f);
    float dcoarse = span * (1.0f / 63.0f);
    float inv_dcoarse = __fdividef(1.0f, dcoarse);   // inf on miss (handled)

    if (miss) {
        ox = clamp1(ox + dx * 1e9f);
        oy = clamp1(oy + dy * 1e9f);
        oz = clamp1(oz + dz * 1e9f);
        dx = 0.0f; dy = 0.0f; dz = 0.0f;
    }

    // ---- per-lane: fold input layer for 2 owned units, emit deltas + init ----
    u64 I0, I1, I2, I3;          // packed init (A,B) for s,r,g,b
    u32 ve, vo;                  // sort elements: (masked float key) | idx
    {
        const float2* W1v = reinterpret_cast<const float2*>(W1);
        float2 ax2 = W1v[lane];
        float2 ay2 = W1v[32 + lane];
        float2 az2 = W1v[64 + lane];
        float2 b2  = reinterpret_cast<const float2*>(b1)[lane];
        int j0 = 2 * lane, j1 = j0 + 1;
        float gs[2], cs[2], wS[2], wR[2], wG[2], wB[2];
        gs[0] = fmaf(ax2.x, dx, fmaf(ay2.x, dy, az2.x * dz));
        gs[1] = fmaf(ax2.y, dx, fmaf(ay2.y, dy, az2.y * dz));
        cs[0] = fmaf(ax2.x, ox, fmaf(ay2.x, oy, fmaf(az2.x, oz, b2.x)));
        cs[1] = fmaf(ax2.y, ox, fmaf(ay2.y, oy, fmaf(az2.y, oz, b2.y)));
        wS[0] = w_sigma[j0];        wS[1] = w_sigma[j1];
        wR[0] = W_rgb[3 * j0];      wR[1] = W_rgb[3 * j1];
        wG[0] = W_rgb[3 * j0 + 1];  wG[1] = W_rgb[3 * j1 + 1];
        wB[0] = W_rgb[3 * j0 + 2];  wB[1] = W_rgb[3 * j1 + 2];

        I0 = 0; I1 = 0; I2 = 0; I3 = 0;
        #pragma unroll
        for (int q = 0; q < 2; q++) {
            float g = gs[q], c = cs[q];
            bool gz  = (g == 0.0f);
            bool neg = (g < 0.0f);
            float zs  = gz ? __int_as_float(0x7f800000) : (-c / g);
            float sgn = gz ? 0.0f : (neg ? -1.0f : 1.0f);
            float relc = fmaxf(c, 0.0f);

            float pS = wS[q] * g, qS = wS[q] * c;
            float pR = wR[q] * g, qR = wR[q] * c;
            float pG = wG[q] * g, qG = wG[q] * c;
            float pB = wB[q] * g, qB = wB[q] * c;

            I0 = add2(I0, pk2(neg ? pS : 0.0f, neg ? qS : (gz ? wS[q] * relc : 0.0f)));
            I1 = add2(I1, pk2(neg ? pR : 0.0f, neg ? qR : (gz ? wR[q] * relc : 0.0f)));
            I2 = add2(I2, pk2(neg ? pG : 0.0f, neg ? qG : (gz ? wG[q] * relc : 0.0f)));
            I3 = add2(I3, pk2(neg ? pB : 0.0f, neg ? qB : (gz ? wB[q] * relc : 0.0f)));

            float4* rowp = reinterpret_cast<float4*>(sBuf[w][j0 + q]);
            rowp[0] = make_float4(sgn * pS, sgn * qS, sgn * pR, sgn * qR);
            rowp[1] = make_float4(sgn * pG, sgn * qG, sgn * pB, sgn * qB);

            u32 key = (ford(zs) & 0xFFFFFFC0u) | (u32)(j0 + q);
            if (q == 0) ve = key; else vo = key;
        }
    }
    __syncwarp();   // delta rows visible before gather

    // add output biases to init B components (uniform across lanes)
    #pragma unroll
    for (int o = 16; o > 0; o >>= 1) {
        I0 = add2(I0, __shfl_xor_sync(FULLMASK, I0, o));
        I1 = add2(I1, __shfl_xor_sync(FULLMASK, I1, o));
        I2 = add2(I2, __shfl_xor_sync(FULLMASK, I2, o));
        I3 = add2(I3, __shfl_xor_sync(FULLMASK, I3, o));
    }
    I0 = add2(I0, pk2(0.0f, bS));
    I1 = add2(I1, pk2(0.0f, bR));
    I2 = add2(I2, pk2(0.0f, bG));
    I3 = add2(I3, pk2(0.0f, bB));

    // ---- bitonic sort of 64 u32 keys; v0 at pos=lane, v1 at pos=lane+32 ----
    u32 v0 = ve, v1 = vo;
    #pragma unroll
    for (int k = 2; k <= 64; k <<= 1) {
        #pragma unroll
        for (int j = k >> 1; j > 0; j >>= 1) {
            if (j == 32) {
                u32 mn = (v0 < v1) ? v0 : v1;
                u32 mx = (v0 < v1) ? v1 : v0;
                v0 = mn; v1 = mx;
            } else {
                u32 p0 = __shfl_xor_sync(FULLMASK, v0, j);
                u32 p1 = __shfl_xor_sync(FULLMASK, v1, j);
                bool lower = ((lane & j) == 0);
                bool up0 = ((lane & k) == 0);
                bool up1 = (((lane + 32) & k) == 0);
                v0 = (((v0 < p0)) == (up0 == lower)) ? v0 : p0;
                v1 = (((v1 < p1)) == (up1 == lower)) ? v1 : p1;
            }
        }
    }

    // ---- gather deltas in sorted order ----
    int idx0 = (int)(v0 & 63u);
    int idx1 = (int)(v1 & 63u);
    ulonglong2 g0a, g0b, g1a, g1b;
    {
        const ulonglong2* p0 = reinterpret_cast<const ulonglong2*>(sBuf[w][idx0]);
        g0a = p0[0]; g0b = p0[1];
        const ulonglong2* p1 = reinterpret_cast<const ulonglong2*>(sBuf[w][idx1]);
        g1a = p1[0]; g1b = p1[1];
    }
    u64 s00 = g0a.x, s01 = g0a.y, s02 = g0b.x, s03 = g0b.y;
    u64 s10 = g1a.x, s11 = g1a.y, s12 = g1b.x, s13 = g1b.y;

    #pragma unroll
    for (int o = 1; o < 32; o <<= 1) {
        u64 t;
        t = __shfl_up_sync(FULLMASK, s00, o); if (lane >= o) s00 = add2(s00, t);
        t = __shfl_up_sync(FULLMASK, s01, o); if (lane >= o) s01 = add2(s01, t);
        t = __shfl_up_sync(FULLMASK, s02, o); if (lane >= o) s02 = add2(s02, t);
        t = __shfl_up_sync(FULLMASK, s03, o); if (lane >= o) s03 = add2(s03, t);
        t = __shfl_up_sync(FULLMASK, s10, o); if (lane >= o) s10 = add2(s10, t);
        t = __shfl_up_sync(FULLMASK, s11, o); if (lane >= o) s11 = add2(s11, t);
        t = __shfl_up_sync(FULLMASK, s12, o); if (lane >= o) s12 = add2(s12, t);
        t = __shfl_up_sync(FULLMASK, s13, o); if (lane >= o) s13 = add2(s13, t);
    }
    s10 = add2(s10, __shfl_sync(FULLMASK, s00, 31));
    s11 = add2(s11, __shfl_sync(FULLMASK, s01, 31));
    s12 = add2(s12, __shfl_sync(FULLMASK, s02, 31));
    s13 = add2(s13, __shfl_sync(FULLMASK, s03, 31));

    __syncwarp();   // all gathers done before overwriting sBuf

    // ---- store prefix table; zero hist (coarse-rank phase) ----
    {
        ulonglong2* e0 = reinterpret_cast<ulonglong2*>(sBuf[w][lane + 1]);
        e0[0] = make_ulonglong2(add2(I0, s00), add2(I1, s01));
        e0[1] = make_ulonglong2(add2(I2, s02), add2(I3, s03));
        ulonglong2* e1 = reinterpret_cast<ulonglong2*>(sBuf[w][lane + 33]);
        e1[0] = make_ulonglong2(add2(I0, s10), add2(I1, s11));
        e1[1] = make_ulonglong2(add2(I2, s12), add2(I3, s13));
        if (lane == 0) {
            ulonglong2* ip = reinterpret_cast<ulonglong2*>(sBuf[w][0]);
            ip[0] = make_ulonglong2(I0, I1);
            ip[1] = make_ulonglong2(I2, I3);
        }
        reinterpret_cast<uint2*>(hist[w])[lane] = make_uint2(0u, 0u);
    }
    __syncwarp();

    // ---- coarse ranks by inverted query: each breakpoint computes its grid
    //      insertion position q = #{t: ford(zg(t)) < key} (arithmetic + fixup) ----
    {
        u32 kk[2] = {v0, v1};
        #pragma unroll
        for (int q = 0; q < 2; q++) {
            u32 key = kk[q];
            float zstar = unford(key);
            int t = __float2int_rd(__fmul_rn(zstar - near, inv_dcoarse));
            t = max(0, min(63, t));
            while (t < 64 && ford(zg(near, span, t)) < key) t++;
            while (t > 0 && ford(zg(near, span, t - 1)) >= key) t--;
            if (t < 64) atomicAdd(&hist[w][t], 1u);
        }
    }
    __syncwarp();

    int tc0 = 2 * lane;
    float z0 = zg(near, span, tc0);
    float z1 = zg(near, span, tc0 + 1);
    int r0, r1;
    {
        uint2 hv = reinterpret_cast<const uint2*>(hist[w])[lane];
        u32 hs = hv.x + hv.y;
        u32 hincl = hs;
        #pragma unroll
        for (int o = 1; o < 32; o <<= 1) {
            u32 t = __shfl_up_sync(FULLMASK, hincl, o);
            if (lane >= o) hincl += t;
        }
        u32 hexcl = __shfl_up_sync(FULLMASK, hincl, 1);
        if (lane == 0) hexcl = 0u;
        r0 = (int)(hexcl + hv.x);
        r1 = (int)(hexcl + hs);
    }

    // ---- coarse sigma + composite ----
    float2 ab0 = *reinterpret_cast<const float2*>(sBuf[w][r0]);
    float2 ab1 = *reinterpret_cast<const float2*>(sBuf[w][r1]);
    float sig0 = softplusf(fmaf(ab0.x, z0, ab0.y));
    float sig1 = softplusf(fmaf(ab1.x, z1, ab1.y));

    float d0 = dcoarse;
    float d1 = (lane == 31) ? sample_dist : dcoarse;
    float q0 = __expf(-d0 * sig0) + 1e-15f;
    float q1 = __expf(-d1 * sig1) + 1e-15f;
    float a0 = 1.0f - (q0 - 1e-15f);
    float a1 = 1.0f - (q1 - 1e-15f);

    float incl = q0 * q1;
    #pragma unroll
    for (int o = 1; o < 32; o <<= 1) {
        float t = __shfl_up_sync(FULLMASK, incl, o);
        if (lane >= o) incl *= t;
    }
    float Texcl = __shfl_up_sync(FULLMASK, incl, 1);
    if (lane == 0) Texcl = 1.0f;
    float w0 = a0 * Texcl;
    float w1 = a1 * Texcl * q0;

    // ---- CDF via warp add-scan (registers only) ----
    float v0f = (lane > 0)  ? (w0 + 1e-5f) : 0.0f;
    float v1f = (lane < 31) ? (w1 + 1e-5f) : 0.0f;
    float lsum = v0f + v1f;
    float sincl = lsum;
    #pragma unroll
    for (int o = 1; o < 32; o <<= 1) {
        float t = __shfl_up_sync(FULLMASK, sincl, o);
        if (lane >= o) sincl += t;
    }
    float sexcl = __shfl_up_sync(FULLMASK, sincl, 1);
    if (lane == 0) sexcl = 0.0f;
    float S = __shfl_sync(FULLMASK, sincl, 31);
    float invS = __fdividef(1.0f, S);

    float cc0 = (sexcl + v0f)  * invS;   // C[tc0]
    float cc1 = (sexcl + lsum) * invS;   // C[tc0+1]
    float cp0 = __shfl_up_sync(FULLMASK, cc1, 1);   // C[tc0-1]

    // zero hist for merge phase
    reinterpret_cast<uint2*>(hist[w])[lane] = make_uint2(0u, 0u);
    __syncwarp();

    // ---- inverse-CDF by arithmetic scatter + rank histogram ----
    #pragma unroll
    for (int p = 0; p < 2; p++) {
        int i = tc0 + p;
        if (i == 0) continue;
        float cp = (p == 0) ? cp0 : cc0;
        bool last = (i == 63);
        float cc = last ? cp : ((p == 0) ? cc0 : cc1);
        float zim1 = zg(near, span, i - 1);
        float zi   = (p == 0) ? z0 : z1;
        float bb = 0.5f * (zim1 + zi);
        float ba = last ? bb : 0.5f * (zi + zg(near, span, i + 1));
        int klo = kfun(cp);
        int khi = last ? 64 : kfun(cc);
        float denom = cc - cp;
        if (denom < 1e-5f) denom = 1.0f;
        for (int k = klo; k < khi; k++) {
            float u = (float)(2 * k + 1) * (1.0f / 128.0f);
            float nzv = bb + (u - cp) / denom * (ba - bb);
            int r = i + ((zi <= nzv) ? 1 : 0);
            zall[w][k + r] = nzv;
            if (r < 64) atomicAdd(&hist[w][r], 1u);
        }
    }
    __syncwarp();

    // ---- place grid points: pos(t) = t + F(t) ----
    {
        uint2 hv = reinterpret_cast<const uint2*>(hist[w])[lane];
        u32 hs = hv.x + hv.y;
        u32 hincl = hs;
        #pragma unroll
        for (int o = 1; o < 32; o <<= 1) {
            u32 t = __shfl_up_sync(FULLMASK, hincl, o);
            if (lane >= o) hincl += t;
        }
        u32 hexcl = __shfl_up_sync(FULLMASK, hincl, 1);
        if (lane == 0) hexcl = 0u;
        zall[w][tc0     + (int)(hexcl + hv.x)] = z0;
        zall[w][tc0 + 1 + (int)(hexcl + hs)]   = z1;
    }
    __syncwarp();

    // ---- fine ranks by inverted query: each breakpoint finds its position in
    //      zall (1 search per breakpoint), ranks from histogram + scan ----
    reinterpret_cast<uint4*>(hist[w])[lane] = make_uint4(0u, 0u, 0u, 0u);
    __syncwarp();
    {
        u32 kk[2] = {v0, v1};
        #pragma unroll
        for (int q = 0; q < 2; q++) {
            u32 key = kk[q];
            int lo = 0, hi = 128;    // p = #{t: ford(zall[t]) < key}
            while (lo < hi) {
                int m = (lo + hi) >> 1;
                if (ford(zall[w][m]) < key) lo = m + 1; else hi = m;
            }
            if (lo < 128) atomicAdd(&hist[w][lo], 1u);
        }
    }
    __syncwarp();

    int rr[4];
    {
        uint4 hv = reinterpret_cast<const uint4*>(hist[w])[lane];
        u32 c0 = hv.x;
        u32 c1 = c0 + hv.y;
        u32 c2 = c1 + hv.z;
        u32 c3 = c2 + hv.w;
        u32 hincl = c3;
        #pragma unroll
        for (int o = 1; o < 32; o <<= 1) {
            u32 t = __shfl_up_sync(FULLMASK, hincl, o);
            if (lane >= o) hincl += t;
        }
        u32 hexcl = __shfl_up_sync(FULLMASK, hincl, 1);
        if (lane == 0) hexcl = 0u;
        rr[0] = (int)(hexcl + c0);
        rr[1] = (int)(hexcl + c1);
        rr[2] = (int)(hexcl + c2);
        rr[3] = (int)(hexcl + c3);
    }

    // ---- fine pass: 4 samples per lane = table row + 4 FMA each ----
    float4 z4 = *reinterpret_cast<const float4*>(&zall[w][4 * lane]);
    float znext = (lane < 31) ? zall[w][4 * lane + 4] : 0.0f;
    float zr[4] = {z4.x, z4.y, z4.z, z4.w};

    float fr[4], fg[4], fb[4], qr[4], al[4], dd[4];
    dd[0] = z4.y - z4.x;
    dd[1] = z4.z - z4.y;
    dd[2] = z4.w - z4.z;
    dd[3] = (lane < 31) ? (znext - z4.w) : sample_dist;
    #pragma unroll
    for (int p = 0; p < 4; p++) {
        const float4* rp = reinterpret_cast<const float4*>(sBuf[w][rr[p]]);
        float4 ra = rp[0];
        float4 rb = rp[1];
        float sg = softplusf(fmaf(ra.x, zr[p], ra.y));
        fr[p] = sigmoidf(fmaf(ra.z, zr[p], ra.w));
        fg[p] = sigmoidf(fmaf(rb.x, zr[p], rb.y));
        fb[p] = sigmoidf(fmaf(rb.z, zr[p], rb.w));
        qr[p] = __expf(-dd[p] * sg) + 1e-15f;
        al[p] = 1.0f - (qr[p] - 1e-15f);
    }

    // ---- fine composite: warp product-scan of transmittance ----
    float fincl = (qr[0] * qr[1]) * (qr[2] * qr[3]);
    #pragma unroll
    for (int o = 1; o < 32; o <<= 1) {
        float t = __shfl_up_sync(FULLMASK, fincl, o);
        if (lane >= o) fincl *= t;
    }
    float T0 = __shfl_up_sync(FULLMASK, fincl, 1);
    if (lane == 0) T0 = 1.0f;
    float T1 = T0 * qr[0];
    float T2 = T1 * qr[1];
    float T3 = T2 * qr[2];

    float wt0 = al[0] * T0, wt1 = al[1] * T1, wt2 = al[2] * T2, wt3 = al[3] * T3;
    float wsum = (wt0 + wt1) + (wt2 + wt3);
    float i0 = fmaf(wt0, fr[0], fmaf(wt1, fr[1], fmaf(wt2, fr[2], wt3 * fr[3])));
    float i1 = fmaf(wt0, fg[0], fmaf(wt1, fg[1], fmaf(wt2, fg[2], wt3 * fg[3])));
    float i2 = fmaf(wt0, fb[0], fmaf(wt1, fb[1], fmaf(wt2, fb[2], wt3 * fb[3])));

    u64 p01 = pk2(i0, i1);
    u64 p2w = pk2(i2, wsum);
    #pragma unroll
    for (int o = 16; o > 0; o >>= 1) {
        p01 = add2(p01, __shfl_xor_sync(FULLMASK, p01, o));
        p2w = add2(p2w, __shfl_xor_sync(FULLMASK, p2w, o));
    }

    if (lane == 0) {
        upk2(p01, i0, i1);
        upk2(p2w, i2, wsum);
        float bg = 1.0f - wsum;
        out[3 * ray + 0] = i0 + bg;
        out[3 * ray + 1] = i1 + bg;
        out[3 * ray + 2] = i2 + bg;
    }
}

extern "C" void kernel_launch(void* const* d_in, const int* in_sizes, int n_in,
                              void* d_out, int out_size) {
    const float* rays_o  = (const float*)d_in[0];
    const float* rays_d  = (const float*)d_in[1];
    const float* W1      = (const float*)d_in[2];
    const float* b1      = (const float*)d_in[3];
    const float* w_sigma = (const float*)d_in[4];
    const float* b_sigma = (const float*)d_in[5];
    const float* W_rgb   = (const float*)d_in[6];
    const float* b_rgb   = (const float*)d_in[7];
    float* out = (float*)d_out;

    nerf_render_kernel<<<BLOCKS, 128>>>(rays_o, rays_d, W1, b1, w_sigma, b_sigma,
                                        W_rgb, b_rgb, out);
}

// round 11
// speedup vs baseline: 1.7206x; 1.7206x over previous
#include <cuda_runtime.h>
#include <cuda_bf16.h>

// NeRF renderer: 16384 rays, 64 coarse + 64 importance samples, 3->64->{1,3} MLP.
// One warp per ray. Piecewise-linear-in-z MLP (affine fold + sorted breakpoints
// + prefix table). R9 structure (arithmetic-scatter CDF + rank-histogram merge)
// plus monotone rank WALKS: one binary search per phase per lane, then 1-LDS
// walks for subsequent samples (ranks are monotone in z).

#define N_RAYS   16384
#define WARPS_PB 4
#define BLOCKS   (N_RAYS / WARPS_PB)
#define FULLMASK 0xffffffffu

typedef unsigned long long u64;
typedef unsigned int u32;

__device__ __forceinline__ u64 pk2(float lo, float hi) {
    u64 r;
    asm("mov.b64 %0, {%1, %2};" : "=l"(r) : "f"(lo), "f"(hi));
    return r;
}
__device__ __forceinline__ void upk2(u64 v, float& lo, float& hi) {
    asm("mov.b64 {%0, %1}, %2;" : "=f"(lo), "=f"(hi) : "l"(v));
}
__device__ __forceinline__ u64 add2(u64 a, u64 b) {
    u64 d;
    asm("add.rn.f32x2 %0, %1, %2;" : "=l"(d) : "l"(a), "l"(b));
    return d;
}

__device__ __forceinline__ float softplusf(float x) {
    return x > 20.0f ? x : __logf(1.0f + __expf(x));
}
__device__ __forceinline__ float sigmoidf(float x) {
    return __fdividef(1.0f, 1.0f + __expf(-x));
}
__device__ __forceinline__ float clamp1(float x) {
    return fminf(fmaxf(x, -1.0f), 1.0f);
}
// order-preserving float->u32 (unsigned compare == float compare)
__device__ __forceinline__ u32 ford(float f) {
    u32 b = __float_as_uint(f);
    return (b & 0x80000000u) ? ~b : (b | 0x80000000u);
}
// Coarse z grid: used identically everywhere.
__device__ __forceinline__ float zg(float near, float span, int i) {
    return __fadd_rn(near, __fmul_rn(span, __fmul_rn((float)i, 1.0f / 63.0f)));
}
// first k with u_k=(2k+1)/128 >= c, clamped to [0,64]
__device__ __forceinline__ int kfun(float c) {
    int k = (int)ceilf(__fmul_rn(64.0f, c) - 0.5f);
    return max(0, min(64, k));
}

__global__ __launch_bounds__(128, 9) void nerf_render_kernel(
    const float* __restrict__ rays_o,
    const float* __restrict__ rays_d,
    const float* __restrict__ W1,      // [3,64]
    const float* __restrict__ b1,      // [64]
    const float* __restrict__ w_sigma, // [64,1]
    const float* __restrict__ b_sigma, // [1]
    const float* __restrict__ W_rgb,   // [64,3]
    const float* __restrict__ b_rgb,   // [3]
    float* __restrict__ out)           // [N_RAYS,3]
{
    // sBuf rows padded to 12 floats (48B).
    // Phase A: rows 0..63 = per-unit delta rows. Phase B: rows 0..64 = prefix table.
    __shared__ __align__(16) float sBuf[WARPS_PB][65][12];
    __shared__ u32 sKey[WARPS_PB][64];   // sorted breakpoint keys
    __shared__ u32 hist[WARPS_PB][64];   // rank histogram for merge
    __shared__ __align__(16) float zall[WARPS_PB][128];

    const int tid  = threadIdx.x;
    const int w    = tid >> 5;
    const int lane = tid & 31;
    const int ray  = blockIdx.x * WARPS_PB + w;

    const float bS = b_sigma[0];
    const float bR = b_rgb[0];
    const float bG = b_rgb[1];
    const float bB = b_rgb[2];

    // ---- ray setup (redundant across lanes) ----
    float ox = rays_o[3 * ray + 0], oy = rays_o[3 * ray + 1], oz = rays_o[3 * ray + 2];
    float dx = rays_d[3 * ray + 0], dy = rays_d[3 * ray + 1], dz = rays_d[3 * ray + 2];
    float inv = rsqrtf(dx * dx + dy * dy + dz * dz);
    dx *= inv; dy *= inv; dz *= inv;

    float t0x = (-1.0f - ox) / (dx + 1e-15f), t1x = (1.0f - ox) / (dx + 1e-15f);
    float t0y = (-1.0f - oy) / (dy + 1e-15f), t1y = (1.0f - oy) / (dy + 1e-15f);
    float t0z = (-1.0f - oz) / (dz + 1e-15f), t1z = (1.0f - oz) / (dz + 1e-15f);
    float lox = fminf(t0x, t1x), hix = fmaxf(t0x, t1x);
    float loy = fminf(t0y, t1y), hiy = fmaxf(t0y, t1y);
    float loz = fminf(t0z, t1z), hiz = fmaxf(t0z, t1z);
    float near = fmaxf(lox, fmaxf(loy, loz));
    float far  = fminf(hix, fminf(hiy, hiz));
    bool miss = (far < near);
    if (miss) { near = 1e9f; far = 1e9f; }
    near = fmaxf(near, 0.05f);
    float span = far - near;
    float sample_dist = span * (1.0f / 64.0f);
    float dcoarse = span * (1.0f / 63.0f);

    if (miss) {
        ox = clamp1(ox + dx * 1e9f);
        oy = clamp1(oy + dy * 1e9f);
        oz = clamp1(oz + dz * 1e9f);
        dx = 0.0f; dy = 0.0f; dz = 0.0f;
    }

    // ---- per-lane: fold input layer for 2 owned units, emit deltas + init ----
    u64 I0, I1, I2, I3;          // packed init (A,B) for s,r,g,b
    u32 ve, vo;                  // sort elements: (masked float key) | idx
    {
        const float2* W1v = reinterpret_cast<const float2*>(W1);
        float2 ax2 = W1v[lane];
        float2 ay2 = W1v[32 + lane];
        float2 az2 = W1v[64 + lane];
        float2 b2  = reinterpret_cast<const float2*>(b1)[lane];
        int j0 = 2 * lane, j1 = j0 + 1;
        float gs[2], cs[2], wS[2], wR[2], wG[2], wB[2];
        gs[0] = fmaf(ax2.x, dx, fmaf(ay2.x, dy, az2.x * dz));
        gs[1] = fmaf(ax2.y, dx, fmaf(ay2.y, dy, az2.y * dz));
        cs[0] = fmaf(ax2.x, ox, fmaf(ay2.x, oy, fmaf(az2.x, oz, b2.x)));
        cs[1] = fmaf(ax2.y, ox, fmaf(ay2.y, oy, fmaf(az2.y, oz, b2.y)));
        wS[0] = w_sigma[j0];        wS[1] = w_sigma[j1];
        wR[0] = W_rgb[3 * j0];      wR[1] = W_rgb[3 * j1];
        wG[0] = W_rgb[3 * j0 + 1];  wG[1] = W_rgb[3 * j1 + 1];
        wB[0] = W_rgb[3 * j0 + 2];  wB[1] = W_rgb[3 * j1 + 2];

        I0 = 0; I1 = 0; I2 = 0; I3 = 0;
        #pragma unroll
        for (int q = 0; q < 2; q++) {
            float g = gs[q], c = cs[q];
            bool gz  = (g == 0.0f);
            bool neg = (g < 0.0f);
            float zs  = gz ? __int_as_float(0x7f800000) : (-c / g);
            float sgn = gz ? 0.0f : (neg ? -1.0f : 1.0f);
            float relc = fmaxf(c, 0.0f);

            float pS = wS[q] * g, qS = wS[q] * c;
            float pR = wR[q] * g, qR = wR[q] * c;
            float pG = wG[q] * g, qG = wG[q] * c;
            float pB = wB[q] * g, qB = wB[q] * c;

            I0 = add2(I0, pk2(neg ? pS : 0.0f, neg ? qS : (gz ? wS[q] * relc : 0.0f)));
            I1 = add2(I1, pk2(neg ? pR : 0.0f, neg ? qR : (gz ? wR[q] * relc : 0.0f)));
            I2 = add2(I2, pk2(neg ? pG : 0.0f, neg ? qG : (gz ? wG[q] * relc : 0.0f)));
            I3 = add2(I3, pk2(neg ? pB : 0.0f, neg ? qB : (gz ? wB[q] * relc : 0.0f)));

            float4* rowp = reinterpret_cast<float4*>(sBuf[w][j0 + q]);
            rowp[0] = make_float4(sgn * pS, sgn * qS, sgn * pR, sgn * qR);
            rowp[1] = make_float4(sgn * pG, sgn * qG, sgn * pB, sgn * qB);

            // u32 sort key: masked float key, idx in low 6 bits (perturbs
            // breakpoint position by <64 ulp in z — negligible, deterministic)
            u32 key = (ford(zs) & 0xFFFFFFC0u) | (u32)(j0 + q);
            if (q == 0) ve = key; else vo = key;
        }
    }
    __syncwarp();   // delta rows visible before gather

    // add output biases to init B components (uniform across lanes)
    #pragma unroll
    for (int o = 16; o > 0; o >>= 1) {
        I0 = add2(I0, __shfl_xor_sync(FULLMASK, I0, o));
        I1 = add2(I1, __shfl_xor_sync(FULLMASK, I1, o));
        I2 = add2(I2, __shfl_xor_sync(FULLMASK, I2, o));
        I3 = add2(I3, __shfl_xor_sync(FULLMASK, I3, o));
    }
    I0 = add2(I0, pk2(0.0f, bS));
    I1 = add2(I1, pk2(0.0f, bR));
    I2 = add2(I2, pk2(0.0f, bG));
    I3 = add2(I3, pk2(0.0f, bB));

    // ---- bitonic sort of 64 u32 keys; v0 at pos=lane, v1 at pos=lane+32 ----
    u32 v0 = ve, v1 = vo;
    #pragma unroll
    for (int k = 2; k <= 64; k <<= 1) {
        #pragma unroll
        for (int j = k >> 1; j > 0; j >>= 1) {
            if (j == 32) {
                u32 mn = (v0 < v1) ? v0 : v1;
                u32 mx = (v0 < v1) ? v1 : v0;
                v0 = mn; v1 = mx;
            } else {
                u32 p0 = __shfl_xor_sync(FULLMASK, v0, j);
                u32 p1 = __shfl_xor_sync(FULLMASK, v1, j);
                bool lower = ((lane & j) == 0);
                bool up0 = ((lane & k) == 0);
                bool up1 = (((lane + 32) & k) == 0);
                v0 = (((v0 < p0)) == (up0 == lower)) ? v0 : p0;
                v1 = (((v1 < p1)) == (up1 == lower)) ? v1 : p1;
            }
        }
    }

    // ---- gather deltas in sorted order ----
    int idx0 = (int)(v0 & 63u);
    int idx1 = (int)(v1 & 63u);
    ulonglong2 g0a, g0b, g1a, g1b;
    {
        const ulonglong2* p0 = reinterpret_cast<const ulonglong2*>(sBuf[w][idx0]);
        g0a = p0[0]; g0b = p0[1];
        const ulonglong2* p1 = reinterpret_cast<const ulonglong2*>(sBuf[w][idx1]);
        g1a = p1[0]; g1b = p1[1];
    }
    u64 s00 = g0a.x, s01 = g0a.y, s02 = g0b.x, s03 = g0b.y;
    u64 s10 = g1a.x, s11 = g1a.y, s12 = g1b.x, s13 = g1b.y;

    #pragma unroll
    for (int o = 1; o < 32; o <<= 1) {
        u64 t;
        t = __shfl_up_sync(FULLMASK, s00, o); if (lane >= o) s00 = add2(s00, t);
        t = __shfl_up_sync(FULLMASK, s01, o); if (lane >= o) s01 = add2(s01, t);
        t = __shfl_up_sync(FULLMASK, s02, o); if (lane >= o) s02 = add2(s02, t);
        t = __shfl_up_sync(FULLMASK, s03, o); if (lane >= o) s03 = add2(s03, t);
        t = __shfl_up_sync(FULLMASK, s10, o); if (lane >= o) s10 = add2(s10, t);
        t = __shfl_up_sync(FULLMASK, s11, o); if (lane >= o) s11 = add2(s11, t);
        t = __shfl_up_sync(FULLMASK, s12, o); if (lane >= o) s12 = add2(s12, t);
        t = __shfl_up_sync(FULLMASK, s13, o); if (lane >= o) s13 = add2(s13, t);
    }
    s10 = add2(s10, __shfl_sync(FULLMASK, s00, 31));
    s11 = add2(s11, __shfl_sync(FULLMASK, s01, 31));
    s12 = add2(s12, __shfl_sync(FULLMASK, s02, 31));
    s13 = add2(s13, __shfl_sync(FULLMASK, s03, 31));

    __syncwarp();   // all gathers done before overwriting sBuf

    // ---- store prefix table + keys; zero merge histogram ----
    {
        ulonglong2* e0 = reinterpret_cast<ulonglong2*>(sBuf[w][lane + 1]);
        e0[0] = make_ulonglong2(add2(I0, s00), add2(I1, s01));
        e0[1] = make_ulonglong2(add2(I2, s02), add2(I3, s03));
        ulonglong2* e1 = reinterpret_cast<ulonglong2*>(sBuf[w][lane + 33]);
        e1[0] = make_ulonglong2(add2(I0, s10), add2(I1, s11));
        e1[1] = make_ulonglong2(add2(I2, s12), add2(I3, s13));
        if (lane == 0) {
            ulonglong2* ip = reinterpret_cast<ulonglong2*>(sBuf[w][0]);
            ip[0] = make_ulonglong2(I0, I1);
            ip[1] = make_ulonglong2(I2, I3);
        }
        sKey[w][lane]      = v0;
        sKey[w][lane + 32] = v1;
        hist[w][lane]      = 0u;
        hist[w][lane + 32] = 0u;
    }
    __syncwarp();

    const u32* keys = sKey[w];
    auto rank_of = [&](float z) -> int {
        u32 kq = ford(z);
        int lo = 0, hi = 64;
        while (lo < hi) { int m = (lo + hi) >> 1; if (keys[m] <= kq) lo = m + 1; else hi = m; }
        return lo;
    };
    // monotone walk from a known lower-bound rank (1 LDS per step)
    auto rank_walk = [&](int r, float z) -> int {
        u32 kq = ford(z);
        while (r < 64 && keys[r] <= kq) r++;
        return r;
    };

    // ---- coarse pass: sigma at 2 grid points per lane ----
    int tc0 = 2 * lane;
    float z0 = zg(near, span, tc0);
    float z1 = zg(near, span, tc0 + 1);
    int r0 = rank_of(z0);
    int r1 = rank_walk(r0, z1);
    float2 ab0 = *reinterpret_cast<const float2*>(sBuf[w][r0]);
    float2 ab1 = *reinterpret_cast<const float2*>(sBuf[w][r1]);
    float sig0 = softplusf(fmaf(ab0.x, z0, ab0.y));
    float sig1 = softplusf(fmaf(ab1.x, z1, ab1.y));

    // ---- coarse composite via warp product-scan ----
    float d0 = dcoarse;
    float d1 = (lane == 31) ? sample_dist : dcoarse;
    float q0 = __expf(-d0 * sig0) + 1e-15f;
    float q1 = __expf(-d1 * sig1) + 1e-15f;
    float a0 = 1.0f - (q0 - 1e-15f);
    float a1 = 1.0f - (q1 - 1e-15f);

    float incl = q0 * q1;
    #pragma unroll
    for (int o = 1; o < 32; o <<= 1) {
        float t = __shfl_up_sync(FULLMASK, incl, o);
        if (lane >= o) incl *= t;
    }
    float Texcl = __shfl_up_sync(FULLMASK, incl, 1);
    if (lane == 0) Texcl = 1.0f;
    float w0 = a0 * Texcl;
    float w1 = a1 * Texcl * q0;

    // ---- CDF via warp add-scan (registers only) ----
    float v0f = (lane > 0)  ? (w0 + 1e-5f) : 0.0f;
    float v1f = (lane < 31) ? (w1 + 1e-5f) : 0.0f;
    float lsum = v0f + v1f;
    float sincl = lsum;
    #pragma unroll
    for (int o = 1; o < 32; o <<= 1) {
        float t = __shfl_up_sync(FULLMASK, sincl, o);
        if (lane >= o) sincl += t;
    }
    float sexcl = __shfl_up_sync(FULLMASK, sincl, 1);
    if (lane == 0) sexcl = 0.0f;
    float S = __shfl_sync(FULLMASK, sincl, 31);
    float invS = __fdividef(1.0f, S);

    // segment boundary CDF values; cp0 passed from previous lane so adjacent
    // lanes partition the k range bitwise-exactly
    float cc0 = (sexcl + v0f)  * invS;   // C[tc0]
    float cc1 = (sexcl + lsum) * invS;   // C[tc0+1]
    float cp0 = __shfl_up_sync(FULLMASK, cc1, 1);   // C[tc0-1]

    // ---- inverse-CDF by arithmetic scatter + rank histogram ----
    #pragma unroll
    for (int p = 0; p < 2; p++) {
        int i = tc0 + p;
        if (i == 0) continue;
        float cp = (p == 0) ? cp0 : cc0;
        bool last = (i == 63);
        float cc = last ? cp : ((p == 0) ? cc0 : cc1);
        float zim1 = zg(near, span, i - 1);
        float zi   = (p == 0) ? z0 : z1;
        float bb = 0.5f * (zim1 + zi);
        float ba = last ? bb : 0.5f * (zi + zg(near, span, i + 1));
        int klo = kfun(cp);
        int khi = last ? 64 : kfun(cc);
        float denom = cc - cp;
        if (denom < 1e-5f) denom = 1.0f;
        for (int k = klo; k < khi; k++) {
            float u = (float)(2 * k + 1) * (1.0f / 128.0f);
            float nzv = bb + (u - cp) / denom * (ba - bb);
            int r = i + ((zi <= nzv) ? 1 : 0);   // grid-rank: nz in (zg(i-1), zg(i+1))
            zall[w][k + r] = nzv;
            if (r < 64) atomicAdd(&hist[w][r], 1u);
        }
    }
    __syncwarp();

    // ---- place grid points: pos(t) = t + F(t), F = cumulative histogram ----
    {
        u32 h0 = hist[w][tc0], h1 = hist[w][tc0 + 1];
        u32 hs = h0 + h1;
        u32 hincl = hs;
        #pragma unroll
        for (int o = 1; o < 32; o <<= 1) {
            u32 t = __shfl_up_sync(FULLMASK, hincl, o);
            if (lane >= o) hincl += t;
        }
        u32 hexcl = __shfl_up_sync(FULLMASK, hincl, 1);
        if (lane == 0) hexcl = 0u;
        zall[w][tc0     + (int)(hexcl + h0)] = z0;
        zall[w][tc0 + 1 + (int)(hexcl + hs)] = z1;
    }
    __syncwarp();

    // ---- fine pass: 1 binary search + 3 monotone walks per lane ----
    float4 z4 = *reinterpret_cast<const float4*>(&zall[w][4 * lane]);
    float znext = (lane < 31) ? zall[w][4 * lane + 4] : 0.0f;
    float zr[4] = {z4.x, z4.y, z4.z, z4.w};

    int rr[4];
    rr[0] = rank_of(zr[0]);
    rr[1] = rank_walk(rr[0], zr[1]);
    rr[2] = rank_walk(rr[1], zr[2]);
    rr[3] = rank_walk(rr[2], zr[3]);

    float fr[4], fg[4], fb[4], qr[4], al[4], dd[4];
    dd[0] = z4.y - z4.x;
    dd[1] = z4.z - z4.y;
    dd[2] = z4.w - z4.z;
    dd[3] = (lane < 31) ? (znext - z4.w) : sample_dist;
    #pragma unroll
    for (int p = 0; p < 4; p++) {
        const float4* rp = reinterpret_cast<const float4*>(sBuf[w][rr[p]]);
        float4 ra = rp[0];
        float4 rb = rp[1];
        float sg = softplusf(fmaf(ra.x, zr[p], ra.y));
        fr[p] = sigmoidf(fmaf(ra.z, zr[p], ra.w));
        fg[p] = sigmoidf(fmaf(rb.x, zr[p], rb.y));
        fb[p] = sigmoidf(fmaf(rb.z, zr[p], rb.w));
        qr[p] = __expf(-dd[p] * sg) + 1e-15f;
        al[p] = 1.0f - (qr[p] - 1e-15f);
    }

    // ---- fine composite: warp product-scan of transmittance ----
    float fincl = (qr[0] * qr[1]) * (qr[2] * qr[3]);
    #pragma unroll
    for (int o = 1; o < 32; o <<= 1) {
        float t = __shfl_up_sync(FULLMASK, fincl, o);
        if (lane >= o) fincl *= t;
    }
    float T0 = __shfl_up_sync(FULLMASK, fincl, 1);
    if (lane == 0) T0 = 1.0f;
    float T1 = T0 * qr[0];
    float T2 = T1 * qr[1];
    float T3 = T2 * qr[2];

    float wt0 = al[0] * T0, wt1 = al[1] * T1, wt2 = al[2] * T2, wt3 = al[3] * T3;
    float wsum = (wt0 + wt1) + (wt2 + wt3);
    float i0 = fmaf(wt0, fr[0], fmaf(wt1, fr[1], fmaf(wt2, fr[2], wt3 * fr[3])));
    float i1 = fmaf(wt0, fg[0], fmaf(wt1, fg[1], fmaf(wt2, fg[2], wt3 * fg[3])));
    float i2 = fmaf(wt0, fb[0], fmaf(wt1, fb[1], fmaf(wt2, fb[2], wt3 * fb[3])));

    u64 p01 = pk2(i0, i1);
    u64 p2w = pk2(i2, wsum);
    #pragma unroll
    for (int o = 16; o > 0; o >>= 1) {
        p01 = add2(p01, __shfl_xor_sync(FULLMASK, p01, o));
        p2w = add2(p2w, __shfl_xor_sync(FULLMASK, p2w, o));
    }

    if (lane == 0) {
        upk2(p01, i0, i1);
        upk2(p2w, i2, wsum);
        float bg = 1.0f - wsum;
        out[3 * ray + 0] = i0 + bg;
        out[3 * ray + 1] = i1 + bg;
        out[3 * ray + 2] = i2 + bg;
    }
}

extern "C" void kernel_launch(void* const* d_in, const int* in_sizes, int n_in,
                              void* d_out, int out_size) {
    const float* rays_o  = (const float*)d_in[0];
    const float* rays_d  = (const float*)d_in[1];
    const float* W1      = (const float*)d_in[2];
    const float* b1      = (const float*)d_in[3];
    const float* w_sigma = (const float*)d_in[4];
    const float* b_sigma = (const float*)d_in[5];
    const float* W_rgb   = (const float*)d_in[6];
    const float* b_rgb   = (const float*)d_in[7];
    float* out = (float*)d_out;

    nerf_render_kernel<<<BLOCKS, 128>>>(rays_o, rays_d, W1, b1, w_sigma, b_sigma,
                                        W_rgb, b_rgb, out);
}

// round 12
// speedup vs baseline: 1.7537x; 1.0193x over previous
#include <cuda_runtime.h>
#include <cuda_bf16.h>

// NeRF renderer: 16384 rays, 64 coarse + 64 importance samples, 3->64->{1,3} MLP.
// One warp per ray. Piecewise-linear-in-z MLP (affine fold + sorted breakpoints
// + prefix table). R11 structure; this round: min-blocks 10 (51-reg cap) for
// occupancy 49% -> ~60%.

#define N_RAYS   16384
#define WARPS_PB 4
#define BLOCKS   (N_RAYS / WARPS_PB)
#define FULLMASK 0xffffffffu

typedef unsigned long long u64;
typedef unsigned int u32;

__device__ __forceinline__ u64 pk2(float lo, float hi) {
    u64 r;
    asm("mov.b64 %0, {%1, %2};" : "=l"(r) : "f"(lo), "f"(hi));
    return r;
}
__device__ __forceinline__ void upk2(u64 v, float& lo, float& hi) {
    asm("mov.b64 {%0, %1}, %2;" : "=f"(lo), "=f"(hi) : "l"(v));
}
__device__ __forceinline__ u64 add2(u64 a, u64 b) {
    u64 d;
    asm("add.rn.f32x2 %0, %1, %2;" : "=l"(d) : "l"(a), "l"(b));
    return d;
}

__device__ __forceinline__ float softplusf(float x) {
    return x > 20.0f ? x : __logf(1.0f + __expf(x));
}
__device__ __forceinline__ float sigmoidf(float x) {
    return __fdividef(1.0f, 1.0f + __expf(-x));
}
__device__ __forceinline__ float clamp1(float x) {
    return fminf(fmaxf(x, -1.0f), 1.0f);
}
// order-preserving float->u32 (unsigned compare == float compare)
__device__ __forceinline__ u32 ford(float f) {
    u32 b = __float_as_uint(f);
    return (b & 0x80000000u) ? ~b : (b | 0x80000000u);
}
// Coarse z grid: used identically everywhere.
__device__ __forceinline__ float zg(float near, float span, int i) {
    return __fadd_rn(near, __fmul_rn(span, __fmul_rn((float)i, 1.0f / 63.0f)));
}
// first k with u_k=(2k+1)/128 >= c, clamped to [0,64]
__device__ __forceinline__ int kfun(float c) {
    int k = (int)ceilf(__fmul_rn(64.0f, c) - 0.5f);
    return max(0, min(64, k));
}

__global__ __launch_bounds__(128, 10) void nerf_render_kernel(
    const float* __restrict__ rays_o,
    const float* __restrict__ rays_d,
    const float* __restrict__ W1,      // [3,64]
    const float* __restrict__ b1,      // [64]
    const float* __restrict__ w_sigma, // [64,1]
    const float* __restrict__ b_sigma, // [1]
    const float* __restrict__ W_rgb,   // [64,3]
    const float* __restrict__ b_rgb,   // [3]
    float* __restrict__ out)           // [N_RAYS,3]
{
    // sBuf rows padded to 12 floats (48B).
    // Phase A: rows 0..63 = per-unit delta rows. Phase B: rows 0..64 = prefix table.
    __shared__ __align__(16) float sBuf[WARPS_PB][65][12];
    __shared__ u32 sKey[WARPS_PB][64];   // sorted breakpoint keys
    __shared__ u32 hist[WARPS_PB][64];   // rank histogram for merge
    __shared__ __align__(16) float zall[WARPS_PB][128];

    const int tid  = threadIdx.x;
    const int w    = tid >> 5;
    const int lane = tid & 31;
    const int ray  = blockIdx.x * WARPS_PB + w;

    const float bS = b_sigma[0];
    const float bR = b_rgb[0];
    const float bG = b_rgb[1];
    const float bB = b_rgb[2];

    // ---- ray setup (redundant across lanes) ----
    float ox = rays_o[3 * ray + 0], oy = rays_o[3 * ray + 1], oz = rays_o[3 * ray + 2];
    float dx = rays_d[3 * ray + 0], dy = rays_d[3 * ray + 1], dz = rays_d[3 * ray + 2];
    float inv = rsqrtf(dx * dx + dy * dy + dz * dz);
    dx *= inv; dy *= inv; dz *= inv;

    float t0x = (-1.0f - ox) / (dx + 1e-15f), t1x = (1.0f - ox) / (dx + 1e-15f);
    float t0y = (-1.0f - oy) / (dy + 1e-15f), t1y = (1.0f - oy) / (dy + 1e-15f);
    float t0z = (-1.0f - oz) / (dz + 1e-15f), t1z = (1.0f - oz) / (dz + 1e-15f);
    float lox = fminf(t0x, t1x), hix = fmaxf(t0x, t1x);
    float loy = fminf(t0y, t1y), hiy = fmaxf(t0y, t1y);
    float loz = fminf(t0z, t1z), hiz = fmaxf(t0z, t1z);
    float near = fmaxf(lox, fmaxf(loy, loz));
    float far  = fminf(hix, fminf(hiy, hiz));
    bool miss = (far < near);
    if (miss) { near = 1e9f; far = 1e9f; }
    near = fmaxf(near, 0.05f);
    float span = far - near;
    float sample_dist = span * (1.0f / 64.0f);
    float dcoarse = span * (1.0f / 63.0f);

    if (miss) {
        ox = clamp1(ox + dx * 1e9f);
        oy = clamp1(oy + dy * 1e9f);
        oz = clamp1(oz + dz * 1e9f);
        dx = 0.0f; dy = 0.0f; dz = 0.0f;
    }

    // ---- per-lane: fold input layer for 2 owned units, emit deltas + init ----
    u64 I0, I1, I2, I3;          // packed init (A,B) for s,r,g,b
    u32 ve, vo;                  // sort elements: (masked float key) | idx
    {
        const float2* W1v = reinterpret_cast<const float2*>(W1);
        float2 ax2 = W1v[lane];
        float2 ay2 = W1v[32 + lane];
        float2 az2 = W1v[64 + lane];
        float2 b2  = reinterpret_cast<const float2*>(b1)[lane];
        int j0 = 2 * lane, j1 = j0 + 1;
        float gs[2], cs[2], wS[2], wR[2], wG[2], wB[2];
        gs[0] = fmaf(ax2.x, dx, fmaf(ay2.x, dy, az2.x * dz));
        gs[1] = fmaf(ax2.y, dx, fmaf(ay2.y, dy, az2.y * dz));
        cs[0] = fmaf(ax2.x, ox, fmaf(ay2.x, oy, fmaf(az2.x, oz, b2.x)));
        cs[1] = fmaf(ax2.y, ox, fmaf(ay2.y, oy, fmaf(az2.y, oz, b2.y)));
        wS[0] = w_sigma[j0];        wS[1] = w_sigma[j1];
        wR[0] = W_rgb[3 * j0];      wR[1] = W_rgb[3 * j1];
        wG[0] = W_rgb[3 * j0 + 1];  wG[1] = W_rgb[3 * j1 + 1];
        wB[0] = W_rgb[3 * j0 + 2];  wB[1] = W_rgb[3 * j1 + 2];

        I0 = 0; I1 = 0; I2 = 0; I3 = 0;
        #pragma unroll
        for (int q = 0; q < 2; q++) {
            float g = gs[q], c = cs[q];
            bool gz  = (g == 0.0f);
            bool neg = (g < 0.0f);
            float zs  = gz ? __int_as_float(0x7f800000) : (-c / g);
            float sgn = gz ? 0.0f : (neg ? -1.0f : 1.0f);
            float relc = fmaxf(c, 0.0f);

            float pS = wS[q] * g, qS = wS[q] * c;
            float pR = wR[q] * g, qR = wR[q] * c;
            float pG = wG[q] * g, qG = wG[q] * c;
            float pB = wB[q] * g, qB = wB[q] * c;

            I0 = add2(I0, pk2(neg ? pS : 0.0f, neg ? qS : (gz ? wS[q] * relc : 0.0f)));
            I1 = add2(I1, pk2(neg ? pR : 0.0f, neg ? qR : (gz ? wR[q] * relc : 0.0f)));
            I2 = add2(I2, pk2(neg ? pG : 0.0f, neg ? qG : (gz ? wG[q] * relc : 0.0f)));
            I3 = add2(I3, pk2(neg ? pB : 0.0f, neg ? qB : (gz ? wB[q] * relc : 0.0f)));

            float4* rowp = reinterpret_cast<float4*>(sBuf[w][j0 + q]);
            rowp[0] = make_float4(sgn * pS, sgn * qS, sgn * pR, sgn * qR);
            rowp[1] = make_float4(sgn * pG, sgn * qG, sgn * pB, sgn * qB);

            u32 key = (ford(zs) & 0xFFFFFFC0u) | (u32)(j0 + q);
            if (q == 0) ve = key; else vo = key;
        }
    }
    __syncwarp();   // delta rows visible before gather

    // add output biases to init B components (uniform across lanes)
    #pragma unroll
    for (int o = 16; o > 0; o >>= 1) {
        I0 = add2(I0, __shfl_xor_sync(FULLMASK, I0, o));
        I1 = add2(I1, __shfl_xor_sync(FULLMASK, I1, o));
        I2 = add2(I2, __shfl_xor_sync(FULLMASK, I2, o));
        I3 = add2(I3, __shfl_xor_sync(FULLMASK, I3, o));
    }
    I0 = add2(I0, pk2(0.0f, bS));
    I1 = add2(I1, pk2(0.0f, bR));
    I2 = add2(I2, pk2(0.0f, bG));
    I3 = add2(I3, pk2(0.0f, bB));

    // ---- bitonic sort of 64 u32 keys; v0 at pos=lane, v1 at pos=lane+32 ----
    u32 v0 = ve, v1 = vo;
    #pragma unroll
    for (int k = 2; k <= 64; k <<= 1) {
        #pragma unroll
        for (int j = k >> 1; j > 0; j >>= 1) {
            if (j == 32) {
                u32 mn = (v0 < v1) ? v0 : v1;
                u32 mx = (v0 < v1) ? v1 : v0;
                v0 = mn; v1 = mx;
            } else {
                u32 p0 = __shfl_xor_sync(FULLMASK, v0, j);
                u32 p1 = __shfl_xor_sync(FULLMASK, v1, j);
                bool lower = ((lane & j) == 0);
                bool up0 = ((lane & k) == 0);
                bool up1 = (((lane + 32) & k) == 0);
                v0 = (((v0 < p0)) == (up0 == lower)) ? v0 : p0;
                v1 = (((v1 < p1)) == (up1 == lower)) ? v1 : p1;
            }
        }
    }

    // ---- gather deltas in sorted order ----
    int idx0 = (int)(v0 & 63u);
    int idx1 = (int)(v1 & 63u);
    ulonglong2 g0a, g0b, g1a, g1b;
    {
        const ulonglong2* p0 = reinterpret_cast<const ulonglong2*>(sBuf[w][idx0]);
        g0a = p0[0]; g0b = p0[1];
        const ulonglong2* p1 = reinterpret_cast<const ulonglong2*>(sBuf[w][idx1]);
        g1a = p1[0]; g1b = p1[1];
    }
    u64 s00 = g0a.x, s01 = g0a.y, s02 = g0b.x, s03 = g0b.y;
    u64 s10 = g1a.x, s11 = g1a.y, s12 = g1b.x, s13 = g1b.y;

    #pragma unroll
    for (int o = 1; o < 32; o <<= 1) {
        u64 t;
        t = __shfl_up_sync(FULLMASK, s00, o); if (lane >= o) s00 = add2(s00, t);
        t = __shfl_up_sync(FULLMASK, s01, o); if (lane >= o) s01 = add2(s01, t);
        t = __shfl_up_sync(FULLMASK, s02, o); if (lane >= o) s02 = add2(s02, t);
        t = __shfl_up_sync(FULLMASK, s03, o); if (lane >= o) s03 = add2(s03, t);
        t = __shfl_up_sync(FULLMASK, s10, o); if (lane >= o) s10 = add2(s10, t);
        t = __shfl_up_sync(FULLMASK, s11, o); if (lane >= o) s11 = add2(s11, t);
        t = __shfl_up_sync(FULLMASK, s12, o); if (lane >= o) s12 = add2(s12, t);
        t = __shfl_up_sync(FULLMASK, s13, o); if (lane >= o) s13 = add2(s13, t);
    }
    s10 = add2(s10, __shfl_sync(FULLMASK, s00, 31));
    s11 = add2(s11, __shfl_sync(FULLMASK, s01, 31));
    s12 = add2(s12, __shfl_sync(FULLMASK, s02, 31));
    s13 = add2(s13, __shfl_sync(FULLMASK, s03, 31));

    __syncwarp();   // all gathers done before overwriting sBuf

    // ---- store prefix table + keys; zero merge histogram ----
    {
        ulonglong2* e0 = reinterpret_cast<ulonglong2*>(sBuf[w][lane + 1]);
        e0[0] = make_ulonglong2(add2(I0, s00), add2(I1, s01));
        e0[1] = make_ulonglong2(add2(I2, s02), add2(I3, s03));
        ulonglong2* e1 = reinterpret_cast<ulonglong2*>(sBuf[w][lane + 33]);
        e1[0] = make_ulonglong2(add2(I0, s10), add2(I1, s11));
        e1[1] = make_ulonglong2(add2(I2, s12), add2(I3, s13));
        if (lane == 0) {
            ulonglong2* ip = reinterpret_cast<ulonglong2*>(sBuf[w][0]);
            ip[0] = make_ulonglong2(I0, I1);
            ip[1] = make_ulonglong2(I2, I3);
        }
        sKey[w][lane]      = v0;
        sKey[w][lane + 32] = v1;
        hist[w][lane]      = 0u;
        hist[w][lane + 32] = 0u;
    }
    __syncwarp();

    const u32* keys = sKey[w];
    auto rank_of = [&](float z) -> int {
        u32 kq = ford(z);
        int lo = 0, hi = 64;
        while (lo < hi) { int m = (lo + hi) >> 1; if (keys[m] <= kq) lo = m + 1; else hi = m; }
        return lo;
    };
    // monotone walk from a known lower-bound rank (1 LDS per step)
    auto rank_walk = [&](int r, float z) -> int {
        u32 kq = ford(z);
        while (r < 64 && keys[r] <= kq) r++;
        return r;
    };

    // ---- coarse pass: sigma at 2 grid points per lane ----
    int tc0 = 2 * lane;
    float z0 = zg(near, span, tc0);
    float z1 = zg(near, span, tc0 + 1);
    int r0 = rank_of(z0);
    int r1 = rank_walk(r0, z1);
    float2 ab0 = *reinterpret_cast<const float2*>(sBuf[w][r0]);
    float2 ab1 = *reinterpret_cast<const float2*>(sBuf[w][r1]);
    float sig0 = softplusf(fmaf(ab0.x, z0, ab0.y));
    float sig1 = softplusf(fmaf(ab1.x, z1, ab1.y));

    // ---- coarse composite via warp product-scan ----
    float d0 = dcoarse;
    float d1 = (lane == 31) ? sample_dist : dcoarse;
    float q0 = __expf(-d0 * sig0) + 1e-15f;
    float q1 = __expf(-d1 * sig1) + 1e-15f;
    float a0 = 1.0f - (q0 - 1e-15f);
    float a1 = 1.0f - (q1 - 1e-15f);

    float incl = q0 * q1;
    #pragma unroll
    for (int o = 1; o < 32; o <<= 1) {
        float t = __shfl_up_sync(FULLMASK, incl, o);
        if (lane >= o) incl *= t;
    }
    float Texcl = __shfl_up_sync(FULLMASK, incl, 1);
    if (lane == 0) Texcl = 1.0f;
    float w0 = a0 * Texcl;
    float w1 = a1 * Texcl * q0;

    // ---- CDF via warp add-scan (registers only) ----
    float v0f = (lane > 0)  ? (w0 + 1e-5f) : 0.0f;
    float v1f = (lane < 31) ? (w1 + 1e-5f) : 0.0f;
    float lsum = v0f + v1f;
    float sincl = lsum;
    #pragma unroll
    for (int o = 1; o < 32; o <<= 1) {
        float t = __shfl_up_sync(FULLMASK, sincl, o);
        if (lane >= o) sincl += t;
    }
    float sexcl = __shfl_up_sync(FULLMASK, sincl, 1);
    if (lane == 0) sexcl = 0.0f;
    float S = __shfl_sync(FULLMASK, sincl, 31);
    float invS = __fdividef(1.0f, S);

    // segment boundary CDF values; cp0 passed from previous lane so adjacent
    // lanes partition the k range bitwise-exactly
    float cc0 = (sexcl + v0f)  * invS;   // C[tc0]
    float cc1 = (sexcl + lsum) * invS;   // C[tc0+1]
    float cp0 = __shfl_up_sync(FULLMASK, cc1, 1);   // C[tc0-1]

    // ---- inverse-CDF by arithmetic scatter + rank histogram ----
    #pragma unroll
    for (int p = 0; p < 2; p++) {
        int i = tc0 + p;
        if (i == 0) continue;
        float cp = (p == 0) ? cp0 : cc0;
        bool last = (i == 63);
        float cc = last ? cp : ((p == 0) ? cc0 : cc1);
        float zim1 = zg(near, span, i - 1);
        float zi   = (p == 0) ? z0 : z1;
        float bb = 0.5f * (zim1 + zi);
        float ba = last ? bb : 0.5f * (zi + zg(near, span, i + 1));
        int klo = kfun(cp);
        int khi = last ? 64 : kfun(cc);
        float denom = cc - cp;
        if (denom < 1e-5f) denom = 1.0f;
        for (int k = klo; k < khi; k++) {
            float u = (float)(2 * k + 1) * (1.0f / 128.0f);
            float nzv = bb + (u - cp) / denom * (ba - bb);
            int r = i + ((zi <= nzv) ? 1 : 0);   // grid-rank: nz in (zg(i-1), zg(i+1))
            zall[w][k + r] = nzv;
            if (r < 64) atomicAdd(&hist[w][r], 1u);
        }
    }
    __syncwarp();

    // ---- place grid points: pos(t) = t + F(t), F = cumulative histogram ----
    {
        u32 h0 = hist[w][tc0], h1 = hist[w][tc0 + 1];
        u32 hs = h0 + h1;
        u32 hincl = hs;
        #pragma unroll
        for (int o = 1; o < 32; o <<= 1) {
            u32 t = __shfl_up_sync(FULLMASK, hincl, o);
            if (lane >= o) hincl += t;
        }
        u32 hexcl = __shfl_up_sync(FULLMASK, hincl, 1);
        if (lane == 0) hexcl = 0u;
        zall[w][tc0     + (int)(hexcl + h0)] = z0;
        zall[w][tc0 + 1 + (int)(hexcl + hs)] = z1;
    }
    __syncwarp();

    // ---- fine pass: 1 binary search + 3 monotone walks per lane ----
    float4 z4 = *reinterpret_cast<const float4*>(&zall[w][4 * lane]);
    float znext = (lane < 31) ? zall[w][4 * lane + 4] : 0.0f;
    float zr[4] = {z4.x, z4.y, z4.z, z4.w};

    int rr[4];
    rr[0] = rank_of(zr[0]);
    rr[1] = rank_walk(rr[0], zr[1]);
    rr[2] = rank_walk(rr[1], zr[2]);
    rr[3] = rank_walk(rr[2], zr[3]);

    float fr[4], fg[4], fb[4], qr[4], al[4], dd[4];
    dd[0] = z4.y - z4.x;
    dd[1] = z4.z - z4.y;
    dd[2] = z4.w - z4.z;
    dd[3] = (lane < 31) ? (znext - z4.w) : sample_dist;
    #pragma unroll
    for (int p = 0; p < 4; p++) {
        const float4* rp = reinterpret_cast<const float4*>(sBuf[w][rr[p]]);
        float4 ra = rp[0];
        float4 rb = rp[1];
        float sg = softplusf(fmaf(ra.x, zr[p], ra.y));
        fr[p] = sigmoidf(fmaf(ra.z, zr[p], ra.w));
        fg[p] = sigmoidf(fmaf(rb.x, zr[p], rb.y));
        fb[p] = sigmoidf(fmaf(rb.z, zr[p], rb.w));
        qr[p] = __expf(-dd[p] * sg) + 1e-15f;
        al[p] = 1.0f - (qr[p] - 1e-15f);
    }

    // ---- fine composite: warp product-scan of transmittance ----
    float fincl = (qr[0] * qr[1]) * (qr[2] * qr[3]);
    #pragma unroll
    for (int o = 1; o < 32; o <<= 1) {
        float t = __shfl_up_sync(FULLMASK, fincl, o);
        if (lane >= o) fincl *= t;
    }
    float T0 = __shfl_up_sync(FULLMASK, fincl, 1);
    if (lane == 0) T0 = 1.0f;
    float T1 = T0 * qr[0];
    float T2 = T1 * qr[1];
    float T3 = T2 * qr[2];

    float wt0 = al[0] * T0, wt1 = al[1] * T1, wt2 = al[2] * T2, wt3 = al[3] * T3;
    float wsum = (wt0 + wt1) + (wt2 + wt3);
    float i0 = fmaf(wt0, fr[0], fmaf(wt1, fr[1], fmaf(wt2, fr[2], wt3 * fr[3])));
    float i1 = fmaf(wt0, fg[0], fmaf(wt1, fg[1], fmaf(wt2, fg[2], wt3 * fg[3])));
    float i2 = fmaf(wt0, fb[0], fmaf(wt1, fb[1], fmaf(wt2, fb[2], wt3 * fb[3])));

    u64 p01 = pk2(i0, i1);
    u64 p2w = pk2(i2, wsum);
    #pragma unroll
    for (int o = 16; o > 0; o >>= 1) {
        p01 = add2(p01, __shfl_xor_sync(FULLMASK, p01, o));
        p2w = add2(p2w, __shfl_xor_sync(FULLMASK, p2w, o));
    }

    if (lane == 0) {
        upk2(p01, i0, i1);
        upk2(p2w, i2, wsum);
        float bg = 1.0f - wsum;
        out[3 * ray + 0] = i0 + bg;
        out[3 * ray + 1] = i1 + bg;
        out[3 * ray + 2] = i2 + bg;
    }
}

extern "C" void kernel_launch(void* const* d_in, const int* in_sizes, int n_in,
                              void* d_out, int out_size) {
    const float* rays_o  = (const float*)d_in[0];
    const float* rays_d  = (const float*)d_in[1];
    const float* W1      = (const float*)d_in[2];
    const float* b1      = (const float*)d_in[3];
    const float* w_sigma = (const float*)d_in[4];
    const float* b_sigma = (const float*)d_in[5];
    const float* W_rgb   = (const float*)d_in[6];
    const float* b_rgb   = (const float*)d_in[7];
    float* out = (float*)d_out;

    nerf_render_kernel<<<BLOCKS, 128>>>(rays_o, rays_d, W1, b1, w_sigma, b_sigma,
                                        W_rgb, b_rgb, out);
}

// round 13
// speedup vs baseline: 1.8141x; 1.0345x over previous
#include <cuda_runtime.h>
#include <cuda_bf16.h>

// NeRF renderer: 16384 rays, 64 coarse + 64 importance samples, 3->64->{1,3} MLP.
// One warp per ray. Piecewise-linear-in-z MLP (affine fold + sorted breakpoints
// + prefix table). This round: BLOCKED bitonic sort (lane owns sorted positions
// 2L,2L+1) so the prefix scan runs once over local pair-sums: u64 scan shuffles
// 176 -> 40, sort shuffles 40 -> 30.

#define N_RAYS   16384
#define WARPS_PB 4
#define BLOCKS   (N_RAYS / WARPS_PB)
#define FULLMASK 0xffffffffu

typedef unsigned long long u64;
typedef unsigned int u32;

__device__ __forceinline__ u64 pk2(float lo, float hi) {
    u64 r;
    asm("mov.b64 %0, {%1, %2};" : "=l"(r) : "f"(lo), "f"(hi));
    return r;
}
__device__ __forceinline__ void upk2(u64 v, float& lo, float& hi) {
    asm("mov.b64 {%0, %1}, %2;" : "=f"(lo), "=f"(hi) : "l"(v));
}
__device__ __forceinline__ u64 add2(u64 a, u64 b) {
    u64 d;
    asm("add.rn.f32x2 %0, %1, %2;" : "=l"(d) : "l"(a), "l"(b));
    return d;
}

__device__ __forceinline__ float softplusf(float x) {
    return x > 20.0f ? x : __logf(1.0f + __expf(x));
}
__device__ __forceinline__ float sigmoidf(float x) {
    return __fdividef(1.0f, 1.0f + __expf(-x));
}
__device__ __forceinline__ float clamp1(float x) {
    return fminf(fmaxf(x, -1.0f), 1.0f);
}
// order-preserving float->u32 (unsigned compare == float compare)
__device__ __forceinline__ u32 ford(float f) {
    u32 b = __float_as_uint(f);
    return (b & 0x80000000u) ? ~b : (b | 0x80000000u);
}
// Coarse z grid: used identically everywhere.
__device__ __forceinline__ float zg(float near, float span, int i) {
    return __fadd_rn(near, __fmul_rn(span, __fmul_rn((float)i, 1.0f / 63.0f)));
}
// first k with u_k=(2k+1)/128 >= c, clamped to [0,64]
__device__ __forceinline__ int kfun(float c) {
    int k = (int)ceilf(__fmul_rn(64.0f, c) - 0.5f);
    return max(0, min(64, k));
}

__global__ __launch_bounds__(128, 10) void nerf_render_kernel(
    const float* __restrict__ rays_o,
    const float* __restrict__ rays_d,
    const float* __restrict__ W1,      // [3,64]
    const float* __restrict__ b1,      // [64]
    const float* __restrict__ w_sigma, // [64,1]
    const float* __restrict__ b_sigma, // [1]
    const float* __restrict__ W_rgb,   // [64,3]
    const float* __restrict__ b_rgb,   // [3]
    float* __restrict__ out)           // [N_RAYS,3]
{
    // sBuf rows padded to 12 floats (48B).
    // Phase A: rows 0..63 = per-unit delta rows. Phase B: rows 0..64 = prefix table.
    __shared__ __align__(16) float sBuf[WARPS_PB][65][12];
    __shared__ __align__(8) u32 sKey[WARPS_PB][64];   // sorted breakpoint keys
    __shared__ u32 hist[WARPS_PB][64];   // rank histogram for merge
    __shared__ __align__(16) float zall[WARPS_PB][128];

    const int tid  = threadIdx.x;
    const int w    = tid >> 5;
    const int lane = tid & 31;
    const int ray  = blockIdx.x * WARPS_PB + w;

    const float bS = b_sigma[0];
    const float bR = b_rgb[0];
    const float bG = b_rgb[1];
    const float bB = b_rgb[2];

    // ---- ray setup (redundant across lanes) ----
    float ox = rays_o[3 * ray + 0], oy = rays_o[3 * ray + 1], oz = rays_o[3 * ray + 2];
    float dx = rays_d[3 * ray + 0], dy = rays_d[3 * ray + 1], dz = rays_d[3 * ray + 2];
    float inv = rsqrtf(dx * dx + dy * dy + dz * dz);
    dx *= inv; dy *= inv; dz *= inv;

    float t0x = (-1.0f - ox) / (dx + 1e-15f), t1x = (1.0f - ox) / (dx + 1e-15f);
    float t0y = (-1.0f - oy) / (dy + 1e-15f), t1y = (1.0f - oy) / (dy + 1e-15f);
    float t0z = (-1.0f - oz) / (dz + 1e-15f), t1z = (1.0f - oz) / (dz + 1e-15f);
    float lox = fminf(t0x, t1x), hix = fmaxf(t0x, t1x);
    float loy = fminf(t0y, t1y), hiy = fmaxf(t0y, t1y);
    float loz = fminf(t0z, t1z), hiz = fmaxf(t0z, t1z);
    float near = fmaxf(lox, fmaxf(loy, loz));
    float far  = fminf(hix, fminf(hiy, hiz));
    bool miss = (far < near);
    if (miss) { near = 1e9f; far = 1e9f; }
    near = fmaxf(near, 0.05f);
    float span = far - near;
    float sample_dist = span * (1.0f / 64.0f);
    float dcoarse = span * (1.0f / 63.0f);

    if (miss) {
        ox = clamp1(ox + dx * 1e9f);
        oy = clamp1(oy + dy * 1e9f);
        oz = clamp1(oz + dz * 1e9f);
        dx = 0.0f; dy = 0.0f; dz = 0.0f;
    }

    // ---- per-lane: fold input layer for 2 owned units, emit deltas + init ----
    u64 I0, I1, I2, I3;          // packed init (A,B) for s,r,g,b
    u32 ve, vo;                  // sort elements: (masked float key) | idx
    {
        const float2* W1v = reinterpret_cast<const float2*>(W1);
        float2 ax2 = W1v[lane];
        float2 ay2 = W1v[32 + lane];
        float2 az2 = W1v[64 + lane];
        float2 b2  = reinterpret_cast<const float2*>(b1)[lane];
        int j0 = 2 * lane, j1 = j0 + 1;
        float gs[2], cs[2], wS[2], wR[2], wG[2], wB[2];
        gs[0] = fmaf(ax2.x, dx, fmaf(ay2.x, dy, az2.x * dz));
        gs[1] = fmaf(ax2.y, dx, fmaf(ay2.y, dy, az2.y * dz));
        cs[0] = fmaf(ax2.x, ox, fmaf(ay2.x, oy, fmaf(az2.x, oz, b2.x)));
        cs[1] = fmaf(ax2.y, ox, fmaf(ay2.y, oy, fmaf(az2.y, oz, b2.y)));
        wS[0] = w_sigma[j0];        wS[1] = w_sigma[j1];
        wR[0] = W_rgb[3 * j0];      wR[1] = W_rgb[3 * j1];
        wG[0] = W_rgb[3 * j0 + 1];  wG[1] = W_rgb[3 * j1 + 1];
        wB[0] = W_rgb[3 * j0 + 2];  wB[1] = W_rgb[3 * j1 + 2];

        I0 = 0; I1 = 0; I2 = 0; I3 = 0;
        #pragma unroll
        for (int q = 0; q < 2; q++) {
            float g = gs[q], c = cs[q];
            bool gz  = (g == 0.0f);
            bool neg = (g < 0.0f);
            float zs  = gz ? __int_as_float(0x7f800000) : (-c / g);
            float sgn = gz ? 0.0f : (neg ? -1.0f : 1.0f);
            float relc = fmaxf(c, 0.0f);

            float pS = wS[q] * g, qS = wS[q] * c;
            float pR = wR[q] * g, qR = wR[q] * c;
            float pG = wG[q] * g, qG = wG[q] * c;
            float pB = wB[q] * g, qB = wB[q] * c;

            I0 = add2(I0, pk2(neg ? pS : 0.0f, neg ? qS : (gz ? wS[q] * relc : 0.0f)));
            I1 = add2(I1, pk2(neg ? pR : 0.0f, neg ? qR : (gz ? wR[q] * relc : 0.0f)));
            I2 = add2(I2, pk2(neg ? pG : 0.0f, neg ? qG : (gz ? wG[q] * relc : 0.0f)));
            I3 = add2(I3, pk2(neg ? pB : 0.0f, neg ? qB : (gz ? wB[q] * relc : 0.0f)));

            float4* rowp = reinterpret_cast<float4*>(sBuf[w][j0 + q]);
            rowp[0] = make_float4(sgn * pS, sgn * qS, sgn * pR, sgn * qR);
            rowp[1] = make_float4(sgn * pG, sgn * qG, sgn * pB, sgn * qB);

            // u32 sort key: masked float key, idx in low 6 bits (perturbs
            // breakpoint position by <64 ulp in z — negligible, deterministic)
            u32 key = (ford(zs) & 0xFFFFFFC0u) | (u32)(j0 + q);
            if (q == 0) ve = key; else vo = key;
        }
    }
    __syncwarp();   // delta rows visible before gather

    // add output biases to init B components (uniform across lanes)
    #pragma unroll
    for (int o = 16; o > 0; o >>= 1) {
        I0 = add2(I0, __shfl_xor_sync(FULLMASK, I0, o));
        I1 = add2(I1, __shfl_xor_sync(FULLMASK, I1, o));
        I2 = add2(I2, __shfl_xor_sync(FULLMASK, I2, o));
        I3 = add2(I3, __shfl_xor_sync(FULLMASK, I3, o));
    }
    I0 = add2(I0, pk2(0.0f, bS));
    I1 = add2(I1, pk2(0.0f, bR));
    I2 = add2(I2, pk2(0.0f, bG));
    I3 = add2(I3, pk2(0.0f, bB));

    // ---- BLOCKED bitonic sort: lane holds sorted positions 2*lane (v0) and
    //      2*lane+1 (v1). Partner of position p at stride j>=2 is lane^(j/2);
    //      the j=1 exchange is register-internal in every merge stage. ----
    u32 v0 = ve, v1 = vo;
    #pragma unroll
    for (int k = 2; k <= 64; k <<= 1) {
        bool up = (((2 * lane) & k) == 0);   // same for both elements (k>=2)
        #pragma unroll
        for (int j = k >> 1; j >= 2; j >>= 1) {
            int lj = j >> 1;
            u32 p0 = __shfl_xor_sync(FULLMASK, v0, lj);
            u32 p1 = __shfl_xor_sync(FULLMASK, v1, lj);
            bool lower = ((lane & lj) == 0);
            v0 = (((v0 < p0)) == (up == lower)) ? v0 : p0;
            v1 = (((v1 < p1)) == (up == lower)) ? v1 : p1;
        }
        // j == 1: in-register exchange of the owned pair
        u32 mn = (v0 < v1) ? v0 : v1;
        u32 mx = (v0 < v1) ? v1 : v0;
        v0 = up ? mn : mx;
        v1 = up ? mx : mn;
    }

    // ---- gather deltas for the two owned (contiguous) sorted positions ----
    int idx0 = (int)(v0 & 63u);
    int idx1 = (int)(v1 & 63u);
    ulonglong2 g0a, g0b, g1a, g1b;
    {
        const ulonglong2* p0 = reinterpret_cast<const ulonglong2*>(sBuf[w][idx0]);
        g0a = p0[0]; g0b = p0[1];
        const ulonglong2* p1 = reinterpret_cast<const ulonglong2*>(sBuf[w][idx1]);
        g1a = p1[0]; g1b = p1[1];
    }
    // local pair sums, then ONE 4xu64 scan
    u64 ps0 = add2(g0a.x, g1a.x);
    u64 ps1 = add2(g0a.y, g1a.y);
    u64 ps2 = add2(g0b.x, g1b.x);
    u64 ps3 = add2(g0b.y, g1b.y);
    u64 in0 = ps0, in1 = ps1, in2 = ps2, in3 = ps3;
    #pragma unroll
    for (int o = 1; o < 32; o <<= 1) {
        u64 t;
        t = __shfl_up_sync(FULLMASK, in0, o); if (lane >= o) in0 = add2(in0, t);
        t = __shfl_up_sync(FULLMASK, in1, o); if (lane >= o) in1 = add2(in1, t);
        t = __shfl_up_sync(FULLMASK, in2, o); if (lane >= o) in2 = add2(in2, t);
        t = __shfl_up_sync(FULLMASK, in3, o); if (lane >= o) in3 = add2(in3, t);
    }
    u64 ex0 = __shfl_up_sync(FULLMASK, in0, 1);
    u64 ex1 = __shfl_up_sync(FULLMASK, in1, 1);
    u64 ex2 = __shfl_up_sync(FULLMASK, in2, 1);
    u64 ex3 = __shfl_up_sync(FULLMASK, in3, 1);
    if (lane == 0) { ex0 = 0; ex1 = 0; ex2 = 0; ex3 = 0; }

    __syncwarp();   // all gathers done before overwriting sBuf

    // ---- store prefix table + keys; zero merge histogram ----
    // entry(r) = Init + sum of first r deltas:
    //   entry(2L+1) = I + ex + row(2L)
    //   entry(2L+2) = I + ex + pairsum
    {
        int tc0 = 2 * lane;
        ulonglong2* eA = reinterpret_cast<ulonglong2*>(sBuf[w][tc0 + 1]);
        eA[0] = make_ulonglong2(add2(I0, add2(ex0, g0a.x)), add2(I1, add2(ex1, g0a.y)));
        eA[1] = make_ulonglong2(add2(I2, add2(ex2, g0b.x)), add2(I3, add2(ex3, g0b.y)));
        ulonglong2* eB = reinterpret_cast<ulonglong2*>(sBuf[w][tc0 + 2]);
        eB[0] = make_ulonglong2(add2(I0, add2(ex0, ps0)), add2(I1, add2(ex1, ps1)));
        eB[1] = make_ulonglong2(add2(I2, add2(ex2, ps2)), add2(I3, add2(ex3, ps3)));
        if (lane == 0) {
            ulonglong2* ip = reinterpret_cast<ulonglong2*>(sBuf[w][0]);
            ip[0] = make_ulonglong2(I0, I1);
            ip[1] = make_ulonglong2(I2, I3);
        }
        reinterpret_cast<uint2*>(sKey[w])[lane] = make_uint2(v0, v1);
        hist[w][lane]      = 0u;
        hist[w][lane + 32] = 0u;
    }
    __syncwarp();

    const u32* keys = sKey[w];
    auto rank_of = [&](float z) -> int {
        u32 kq = ford(z);
        int lo = 0, hi = 64;
        while (lo < hi) { int m = (lo + hi) >> 1; if (keys[m] <= kq) lo = m + 1; else hi = m; }
        return lo;
    };
    // monotone walk from a known lower-bound rank (1 LDS per step)
    auto rank_walk = [&](int r, float z) -> int {
        u32 kq = ford(z);
        while (r < 64 && keys[r] <= kq) r++;
        return r;
    };

    // ---- coarse pass: sigma at 2 grid points per lane ----
    int tc0 = 2 * lane;
    float z0 = zg(near, span, tc0);
    float z1 = zg(near, span, tc0 + 1);
    int r0 = rank_of(z0);
    int r1 = rank_walk(r0, z1);
    float2 ab0 = *reinterpret_cast<const float2*>(sBuf[w][r0]);
    float2 ab1 = *reinterpret_cast<const float2*>(sBuf[w][r1]);
    float sig0 = softplusf(fmaf(ab0.x, z0, ab0.y));
    float sig1 = softplusf(fmaf(ab1.x, z1, ab1.y));

    // ---- coarse composite via warp product-scan ----
    float d0 = dcoarse;
    float d1 = (lane == 31) ? sample_dist : dcoarse;
    float q0 = __expf(-d0 * sig0) + 1e-15f;
    float q1 = __expf(-d1 * sig1) + 1e-15f;
    float a0 = 1.0f - (q0 - 1e-15f);
    float a1 = 1.0f - (q1 - 1e-15f);

    float incl = q0 * q1;
    #pragma unroll
    for (int o = 1; o < 32; o <<= 1) {
        float t = __shfl_up_sync(FULLMASK, incl, o);
        if (lane >= o) incl *= t;
    }
    float Texcl = __shfl_up_sync(FULLMASK, incl, 1);
    if (lane == 0) Texcl = 1.0f;
    float w0 = a0 * Texcl;
    float w1 = a1 * Texcl * q0;

    // ---- CDF via warp add-scan (registers only) ----
    float v0f = (lane > 0)  ? (w0 + 1e-5f) : 0.0f;
    float v1f = (lane < 31) ? (w1 + 1e-5f) : 0.0f;
    float lsum = v0f + v1f;
    float sincl = lsum;
    #pragma unroll
    for (int o = 1; o < 32; o <<= 1) {
        float t = __shfl_up_sync(FULLMASK, sincl, o);
        if (lane >= o) sincl += t;
    }
    float sexcl = __shfl_up_sync(FULLMASK, sincl, 1);
    if (lane == 0) sexcl = 0.0f;
    float S = __shfl_sync(FULLMASK, sincl, 31);
    float invS = __fdividef(1.0f, S);

    // segment boundary CDF values; cp0 passed from previous lane so adjacent
    // lanes partition the k range bitwise-exactly
    float cc0 = (sexcl + v0f)  * invS;   // C[tc0]
    float cc1 = (sexcl + lsum) * invS;   // C[tc0+1]
    float cp0 = __shfl_up_sync(FULLMASK, cc1, 1);   // C[tc0-1]

    // ---- inverse-CDF by arithmetic scatter + rank histogram ----
    #pragma unroll
    for (int p = 0; p < 2; p++) {
        int i = tc0 + p;
        if (i == 0) continue;
        float cp = (p == 0) ? cp0 : cc0;
        bool last = (i == 63);
        float cc = last ? cp : ((p == 0) ? cc0 : cc1);
        float zim1 = zg(near, span, i - 1);
        float zi   = (p == 0) ? z0 : z1;
        float bb = 0.5f * (zim1 + zi);
        float ba = last ? bb : 0.5f * (zi + zg(near, span, i + 1));
        int klo = kfun(cp);
        int khi = last ? 64 : kfun(cc);
        float denom = cc - cp;
        if (denom < 1e-5f) denom = 1.0f;
        for (int k = klo; k < khi; k++) {
            float u = (float)(2 * k + 1) * (1.0f / 128.0f);
            float nzv = bb + (u - cp) / denom * (ba - bb);
            int r = i + ((zi <= nzv) ? 1 : 0);   // grid-rank: nz in (zg(i-1), zg(i+1))
            zall[w][k + r] = nzv;
            if (r < 64) atomicAdd(&hist[w][r], 1u);
        }
    }
    __syncwarp();

    // ---- place grid points: pos(t) = t + F(t), F = cumulative histogram ----
    {
        u32 h0 = hist[w][tc0], h1 = hist[w][tc0 + 1];
        u32 hs = h0 + h1;
        u32 hincl = hs;
        #pragma unroll
        for (int o = 1; o < 32; o <<= 1) {
            u32 t = __shfl_up_sync(FULLMASK, hincl, o);
            if (lane >= o) hincl += t;
        }
        u32 hexcl = __shfl_up_sync(FULLMASK, hincl, 1);
        if (lane == 0) hexcl = 0u;
        zall[w][tc0     + (int)(hexcl + h0)] = z0;
        zall[w][tc0 + 1 + (int)(hexcl + hs)] = z1;
    }
    __syncwarp();

    // ---- fine pass: 1 binary search + 3 monotone walks per lane ----
    float4 z4 = *reinterpret_cast<const float4*>(&zall[w][4 * lane]);
    float znext = (lane < 31) ? zall[w][4 * lane + 4] : 0.0f;
    float zr[4] = {z4.x, z4.y, z4.z, z4.w};

    int rr[4];
    rr[0] = rank_of(zr[0]);
    rr[1] = rank_walk(rr[0], zr[1]);
    rr[2] = rank_walk(rr[1], zr[2]);
    rr[3] = rank_walk(rr[2], zr[3]);

    float fr[4], fg[4], fb[4], qr[4], al[4], dd[4];
    dd[0] = z4.y - z4.x;
    dd[1] = z4.z - z4.y;
    dd[2] = z4.w - z4.z;
    dd[3] = (lane < 31) ? (znext - z4.w) : sample_dist;
    #pragma unroll
    for (int p = 0; p < 4; p++) {
        const float4* rp = reinterpret_cast<const float4*>(sBuf[w][rr[p]]);
        float4 ra = rp[0];
        float4 rb = rp[1];
        float sg = softplusf(fmaf(ra.x, zr[p], ra.y));
        fr[p] = sigmoidf(fmaf(ra.z, zr[p], ra.w));
        fg[p] = sigmoidf(fmaf(rb.x, zr[p], rb.y));
        fb[p] = sigmoidf(fmaf(rb.z, zr[p], rb.w));
        qr[p] = __expf(-dd[p] * sg) + 1e-15f;
        al[p] = 1.0f - (qr[p] - 1e-15f);
    }

    // ---- fine composite: warp product-scan of transmittance ----
    float fincl = (qr[0] * qr[1]) * (qr[2] * qr[3]);
    #pragma unroll
    for (int o = 1; o < 32; o <<= 1) {
        float t = __shfl_up_sync(FULLMASK, fincl, o);
        if (lane >= o) fincl *= t;
    }
    float T0 = __shfl_up_sync(FULLMASK, fincl, 1);
    if (lane == 0) T0 = 1.0f;
    float T1 = T0 * qr[0];
    float T2 = T1 * qr[1];
    float T3 = T2 * qr[2];

    float wt0 = al[0] * T0, wt1 = al[1] * T1, wt2 = al[2] * T2, wt3 = al[3] * T3;
    float wsum = (wt0 + wt1) + (wt2 + wt3);
    float i0 = fmaf(wt0, fr[0], fmaf(wt1, fr[1], fmaf(wt2, fr[2], wt3 * fr[3])));
    float i1 = fmaf(wt0, fg[0], fmaf(wt1, fg[1], fmaf(wt2, fg[2], wt3 * fg[3])));
    float i2 = fmaf(wt0, fb[0], fmaf(wt1, fb[1], fmaf(wt2, fb[2], wt3 * fb[3])));

    u64 p01 = pk2(i0, i1);
    u64 p2w = pk2(i2, wsum);
    #pragma unroll
    for (int o = 16; o > 0; o >>= 1) {
        p01 = add2(p01, __shfl_xor_sync(FULLMASK, p01, o));
        p2w = add2(p2w, __shfl_xor_sync(FULLMASK, p2w, o));
    }

    if (lane == 0) {
        upk2(p01, i0, i1);
        upk2(p2w, i2, wsum);
        float bg = 1.0f - wsum;
        out[3 * ray + 0] = i0 + bg;
        out[3 * ray + 1] = i1 + bg;
        out[3 * ray + 2] = i2 + bg;
    }
}

extern "C" void kernel_launch(void* const* d_in, const int* in_sizes, int n_in,
                              void* d_out, int out_size) {
    const float* rays_o  = (const float*)d_in[0];
    const float* rays_d  = (const float*)d_in[1];
    const float* W1      = (const float*)d_in[2];
    const float* b1      = (const float*)d_in[3];
    const float* w_sigma = (const float*)d_in[4];
    const float* b_sigma = (const float*)d_in[5];
    const float* W_rgb   = (const float*)d_in[6];
    const float* b_rgb   = (const float*)d_in[7];
    float* out = (float*)d_out;

    nerf_render_kernel<<<BLOCKS, 128>>>(rays_o, rays_d, W1, b1, w_sigma, b_sigma,
                                        W_rgb, b_rgb, out);
}